// round 16
// baseline (speedup 1.0000x reference)
#include <cuda_runtime.h>
#include <cuda_bf16.h>
#include <cstdint>
#include <cstddef>

// Problem constants
#define T_SEQ 2048
#define D_MODEL 3584
#define HQ 28
#define HKV 4
#define DH 128
#define QKV_N 4608
#define K_OFF 3584
#define V_OFF 4096

#define W_QKV_ELEMS ((size_t)D_MODEL * QKV_N)
#define W_O_ELEMS   ((size_t)D_MODEL * D_MODEL)
#define HID_ELEMS   ((size_t)T_SEQ * D_MODEL)

// Scratch (__device__ globals per allocation-free rule)
__device__ float g_qkv[(size_t)T_SEQ * QKV_N];
__device__ float g_attn[HID_ELEMS];
__device__ __nv_bfloat16 g_WqkvT_h[W_QKV_ELEMS];   // [QKV_N][D_MODEL] transposed
__device__ __nv_bfloat16 g_WqkvT_l[W_QKV_ELEMS];
__device__ __nv_bfloat16 g_WoT_h[W_O_ELEMS];       // [D_MODEL][D_MODEL] transposed
__device__ __nv_bfloat16 g_WoT_l[W_O_ELEMS];
__device__ __nv_bfloat16 g_hid_h[HID_ELEMS];
__device__ __nv_bfloat16 g_hid_l[HID_ELEMS];
__device__ __nv_bfloat16 g_att_h[HID_ELEMS];
__device__ __nv_bfloat16 g_att_l[HID_ELEMS];

// ---------------------------------------------------------------------------
// bf16 split: x = hi + lo (both bf16), fp32-class when 3 cross products kept.
// ---------------------------------------------------------------------------
__device__ __forceinline__ void splitb(float x, __nv_bfloat16& h, __nv_bfloat16& l)
{
    __nv_bfloat16 hh = __float2bfloat16_rn(x);
    float lf = x - __bfloat162float(hh);
    h = hh;
    l = __float2bfloat16_rn(lf);
}

__global__ __launch_bounds__(256) void splitb_kernel(
    const float* __restrict__ x, __nv_bfloat16* __restrict__ hi,
    __nv_bfloat16* __restrict__ lo, size_t n4)
{
    size_t i = (size_t)blockIdx.x * 256 + threadIdx.x;
    if (i >= n4) return;
    float4 v = *(const float4*)(x + i * 4);
    __nv_bfloat16 h[4], l[4];
    splitb(v.x, h[0], l[0]);
    splitb(v.y, h[1], l[1]);
    splitb(v.z, h[2], l[2]);
    splitb(v.w, h[3], l[3]);
    *(uint2*)(hi + i * 4) = *(uint2*)h;
    *(uint2*)(lo + i * 4) = *(uint2*)l;
}

// transpose + split: W[K][N] -> Th/Tl[N][K] (bf16)
__global__ __launch_bounds__(256) void tsplitb_kernel(
    const float* __restrict__ W, __nv_bfloat16* __restrict__ Th,
    __nv_bfloat16* __restrict__ Tl, int K, int N)
{
    __shared__ float t[32][33];
    const int tx = threadIdx.x;       // 0..31
    const int ty = threadIdx.y;       // 0..7
    const int n0 = blockIdx.x * 32;
    const int k0 = blockIdx.y * 32;
#pragma unroll
    for (int i = 0; i < 4; ++i) {
        int kk = ty + i * 8;
        t[kk][tx] = W[(size_t)(k0 + kk) * N + n0 + tx];
    }
    __syncthreads();
#pragma unroll
    for (int i = 0; i < 4; ++i) {
        int nn = ty + i * 8;
        __nv_bfloat16 h, l;
        splitb(t[tx][nn], h, l);
        Th[(size_t)(n0 + nn) * K + k0 + tx] = h;
        Tl[(size_t)(n0 + nn) * K + k0 + tx] = l;
    }
}

// ---------------------------------------------------------------------------
// 3xBF16 GEMM via mma.sync.m16n8k16 (legacy tensor pipe — sm_103 target safe).
// C[M,N] = A[M,K] @ Bt[N,K]^T (+bias)
// BM=BN=128, BK=32, 256 threads = 8 warps (2m x 4n), warp tile 64x32.
// Both A and Bt are [row][K] bf16, so tiles load identically.
// 2-stage cp.async double buffer (R7-proven pipeline).
// AST=40 bf16 -> 80B row stride: 16B-aligned for cp.async,
// and 8 fragment rows hit banks {0,20,8,28,16,4,24,12} (mod 32) = conflict-free.
// ---------------------------------------------------------------------------
#define BK 32
#define AST 40                         // bf16 stride per row (80B = 16*5)
#define TILE_BYTES (128 * AST * 2)     // 10240 B per tile
#define STAGE_BYTES (4 * TILE_BYTES)   // Ah, Al, Bh, Bl = 40960 B
#define GEMM_SMEM_BYTES (2 * STAGE_BYTES)

__device__ __forceinline__ void cp16(uint32_t saddr, const void* g)
{
    asm volatile("cp.async.cg.shared.global [%0], [%1], 16;" :: "r"(saddr), "l"(g));
}

__device__ __forceinline__ void mma_bf16(float* c, const uint32_t* a, const uint32_t* b)
{
    asm volatile(
        "mma.sync.aligned.m16n8k16.row.col.f32.bf16.bf16.f32 "
        "{%0,%1,%2,%3}, {%4,%5,%6,%7}, {%8,%9}, {%0,%1,%2,%3};"
        : "+f"(c[0]), "+f"(c[1]), "+f"(c[2]), "+f"(c[3])
        : "r"(a[0]), "r"(a[1]), "r"(a[2]), "r"(a[3]), "r"(b[0]), "r"(b[1]));
}

__global__ __launch_bounds__(256, 2) void bf3_gemm_kernel(
    const __nv_bfloat16* __restrict__ Ah, const __nv_bfloat16* __restrict__ Al,
    const __nv_bfloat16* __restrict__ Bh, const __nv_bfloat16* __restrict__ Bl,
    const float* __restrict__ bias, float* __restrict__ C,
    int M, int Ndim, int K)
{
    extern __shared__ char smem_c[];

    const int bx = blockIdx.x;
    const int by = blockIdx.y;
    const int tid = threadIdx.x;
    const int wid = tid >> 5;
    const int lane = tid & 31;
    const int warp_m = wid & 1;
    const int warp_n = wid >> 1;
    const int lr = lane >> 2;   // 0..7
    const int lc = lane & 3;    // 0..3

    float acc[4][4][4];
#pragma unroll
    for (int i = 0; i < 4; ++i)
#pragma unroll
        for (int j = 0; j < 4; ++j)
#pragma unroll
            for (int r = 0; r < 4; ++r) acc[i][j][r] = 0.f;

    const uint32_t sbase = (uint32_t)__cvta_generic_to_shared(smem_c);

    // per-stage cp.async: 512 chunks (16B) per tile, 4 tiles, 256 threads -> 8 chunks/thread
#define ISSUE(IT, STG) do {                                                    \
    int k0_ = (IT) * BK;                                                       \
    uint32_t sb_ = sbase + (STG) * STAGE_BYTES;                                \
    _Pragma("unroll")                                                          \
    for (int q_ = 0; q_ < 2; ++q_) {                                           \
        int c_ = tid * 2 + q_;              /* 0..511 */                       \
        int row_ = c_ >> 2;                 /* 0..127 */                       \
        int kc_ = (c_ & 3);                 /* 16B chunk = 8 bf16 */           \
        uint32_t so_ = row_ * (AST * 2) + kc_ * 16;                            \
        size_t ga_ = (size_t)(by * 128 + row_) * K + k0_ + kc_ * 8;            \
        size_t gb_ = (size_t)(bx * 128 + row_) * K + k0_ + kc_ * 8;            \
        cp16(sb_ + so_, Ah + ga_);                                             \
        cp16(sb_ + TILE_BYTES + so_, Al + ga_);                                \
        cp16(sb_ + 2 * TILE_BYTES + so_, Bh + gb_);                            \
        cp16(sb_ + 3 * TILE_BYTES + so_, Bl + gb_);                            \
    }                                                                          \
    asm volatile("cp.async.commit_group;");                                    \
} while (0)

    const int nIter = K / BK;
    ISSUE(0, 0);
    int buf = 0;

    for (int it = 0; it < nIter; ++it) {
        if (it + 1 < nIter) {
            ISSUE(it + 1, buf ^ 1);
            asm volatile("cp.async.wait_group 1;");
        } else {
            asm volatile("cp.async.wait_group 0;");
        }
        __syncthreads();

        const __nv_bfloat16* sAh = (const __nv_bfloat16*)(smem_c + buf * STAGE_BYTES);
        const __nv_bfloat16* sAl = (const __nv_bfloat16*)(smem_c + buf * STAGE_BYTES + TILE_BYTES);
        const __nv_bfloat16* sBh = (const __nv_bfloat16*)(smem_c + buf * STAGE_BYTES + 2 * TILE_BYTES);
        const __nv_bfloat16* sBl = (const __nv_bfloat16*)(smem_c + buf * STAGE_BYTES + 3 * TILE_BYTES);

#pragma unroll
        for (int ks = 0; ks < BK; ks += 16) {
            // A fragments: 4 m-tiles, hi+lo.  reg = u32 pair of consecutive k.
            uint32_t ah[4][4], al[4][4];
#pragma unroll
            for (int mt = 0; mt < 4; ++mt) {
                int m0 = warp_m * 64 + mt * 16;
                const __nv_bfloat16* r0h = sAh + (m0 + lr) * AST + ks + lc * 2;
                const __nv_bfloat16* r1h = sAh + (m0 + lr + 8) * AST + ks + lc * 2;
                const __nv_bfloat16* r0l = sAl + (m0 + lr) * AST + ks + lc * 2;
                const __nv_bfloat16* r1l = sAl + (m0 + lr + 8) * AST + ks + lc * 2;
                ah[mt][0] = *(const uint32_t*)(r0h);
                ah[mt][1] = *(const uint32_t*)(r1h);
                ah[mt][2] = *(const uint32_t*)(r0h + 8);
                ah[mt][3] = *(const uint32_t*)(r1h + 8);
                al[mt][0] = *(const uint32_t*)(r0l);
                al[mt][1] = *(const uint32_t*)(r1l);
                al[mt][2] = *(const uint32_t*)(r0l + 8);
                al[mt][3] = *(const uint32_t*)(r1l + 8);
            }
            // B fragments: 4 n-tiles, hi+lo (Bt stored [n][k])
            uint32_t bh[4][2], bl[4][2];
#pragma unroll
            for (int nt = 0; nt < 4; ++nt) {
                int n0 = warp_n * 32 + nt * 8;
                const __nv_bfloat16* c0h = sBh + (n0 + lr) * AST + ks + lc * 2;
                const __nv_bfloat16* c0l = sBl + (n0 + lr) * AST + ks + lc * 2;
                bh[nt][0] = *(const uint32_t*)(c0h);
                bh[nt][1] = *(const uint32_t*)(c0h + 8);
                bl[nt][0] = *(const uint32_t*)(c0l);
                bl[nt][1] = *(const uint32_t*)(c0l + 8);
            }
#pragma unroll
            for (int mt = 0; mt < 4; ++mt)
#pragma unroll
                for (int nt = 0; nt < 4; ++nt) {
                    mma_bf16(acc[mt][nt], ah[mt], bl[nt]);   // hi*lo
                    mma_bf16(acc[mt][nt], al[mt], bh[nt]);   // lo*hi
                    mma_bf16(acc[mt][nt], ah[mt], bh[nt]);   // hi*hi
                }
        }
        __syncthreads();
        buf ^= 1;
    }

#pragma unroll
    for (int mt = 0; mt < 4; ++mt) {
        int row = by * 128 + warp_m * 64 + mt * 16 + lr;
#pragma unroll
        for (int nt = 0; nt < 4; ++nt) {
            int col = bx * 128 + warp_n * 32 + nt * 8 + lc * 2;
            float bv0 = 0.f, bv1 = 0.f;
            if (bias) { bv0 = bias[col]; bv1 = bias[col + 1]; }
            float2 r0 = make_float2(acc[mt][nt][0] + bv0, acc[mt][nt][1] + bv1);
            float2 r1 = make_float2(acc[mt][nt][2] + bv0, acc[mt][nt][3] + bv1);
            *(float2*)&C[(size_t)row * Ndim + col] = r0;
            *(float2*)&C[(size_t)(row + 8) * Ndim + col] = r1;
        }
    }
}

// ---------------------------------------------------------------------------
// RoPE (unchanged)
// ---------------------------------------------------------------------------
__global__ __launch_bounds__(256) void rope_kernel(const int* __restrict__ pos,
                                                   float* __restrict__ qkv)
{
    int idx = blockIdx.x * 256 + threadIdx.x;
    int j = idx & 63;
    int h = (idx >> 6) & 31;
    int t = idx >> 11;
    if (t >= T_SEQ) return;

    float inv_freq = expf(-13.815510557964274f * (float)j * (1.0f / 64.0f));
    float ang = (float)pos[t] * inv_freq;
    float s, c;
    sincosf(ang, &s, &c);

    size_t base;
    if (h < HQ) base = (size_t)t * QKV_N + (size_t)h * DH;
    else        base = (size_t)t * QKV_N + K_OFF + (size_t)(h - HQ) * DH;

    float x1 = qkv[base + j];
    float x2 = qkv[base + 64 + j];
    qkv[base + j]      = x1 * c - x2 * s;
    qkv[base + 64 + j] = x2 * c + x1 * s;
}

// ---------------------------------------------------------------------------
// Flash attention (unchanged from R5 baseline)
// ---------------------------------------------------------------------------
#define FBM 64
#define FBN 64
#define QS_PAD 68
#define FLASH_SMEM_FLOATS (128 * QS_PAD * 2 + FBN * DH + FBM * QS_PAD)
#define FLASH_SMEM_BYTES (FLASH_SMEM_FLOATS * 4)

__global__ __launch_bounds__(256) void flash_kernel(const float* __restrict__ qkv,
                                                    float* __restrict__ attn)
{
    extern __shared__ float sm[];
    float* Qs = sm;
    float* Ks = Qs + 128 * QS_PAD;
    float* Vs = Ks + 128 * QS_PAD;
    float* Ps = Vs + FBN * DH;

    const int qt = blockIdx.x;
    const int h = blockIdx.y;
    const int hkv = h / 7;
    const int tid = threadIdx.x;
    const int tx = tid & 15;
    const int ty = tid >> 4;
    const float scale = 0.08838834764831845f;

    for (int idx = tid; idx < FBM * 32; idx += 256) {
        int m = idx >> 5;
        int k4 = (idx & 31) << 2;
        float4 v = *(const float4*)&qkv[(size_t)(qt * FBM + m) * QKV_N + h * DH + k4];
        Qs[(k4 + 0) * QS_PAD + m] = v.x;
        Qs[(k4 + 1) * QS_PAD + m] = v.y;
        Qs[(k4 + 2) * QS_PAD + m] = v.z;
        Qs[(k4 + 3) * QS_PAD + m] = v.w;
    }

    float o[4][8];
    float mrow[4], lrow[4];
#pragma unroll
    for (int i = 0; i < 4; ++i) {
        mrow[i] = -1e30f;
        lrow[i] = 0.f;
#pragma unroll
        for (int d = 0; d < 8; ++d) o[i][d] = 0.f;
    }

    for (int kt = 0; kt <= qt; ++kt) {
        __syncthreads();
        for (int idx = tid; idx < FBN * 32; idx += 256) {
            int r = idx >> 5;
            int k4 = (idx & 31) << 2;
            size_t base = (size_t)(kt * FBN + r) * QKV_N;
            float4 kv = *(const float4*)&qkv[base + K_OFF + hkv * DH + k4];
            Ks[(k4 + 0) * QS_PAD + r] = kv.x;
            Ks[(k4 + 1) * QS_PAD + r] = kv.y;
            Ks[(k4 + 2) * QS_PAD + r] = kv.z;
            Ks[(k4 + 3) * QS_PAD + r] = kv.w;
            float4 vv = *(const float4*)&qkv[base + V_OFF + hkv * DH + k4];
            *(float4*)&Vs[r * DH + k4] = vv;
        }
        __syncthreads();

        float s[4][4];
#pragma unroll
        for (int i = 0; i < 4; ++i)
#pragma unroll
            for (int j = 0; j < 4; ++j) s[i][j] = 0.f;

        for (int k = 0; k < DH; ++k) {
            float4 a = *(const float4*)&Qs[k * QS_PAD + 4 * ty];
            float4 b = *(const float4*)&Ks[k * QS_PAD + 4 * tx];
            float av[4] = {a.x, a.y, a.z, a.w};
            float bv[4] = {b.x, b.y, b.z, b.w};
#pragma unroll
            for (int i = 0; i < 4; ++i)
#pragma unroll
                for (int j = 0; j < 4; ++j)
                    s[i][j] += av[i] * bv[j];
        }

        const bool diag = (kt == qt);
#pragma unroll
        for (int i = 0; i < 4; ++i)
#pragma unroll
            for (int j = 0; j < 4; ++j) {
                float v = s[i][j] * scale;
                if (diag && (4 * tx + j) > (4 * ty + i)) v = -1e30f;
                s[i][j] = v;
            }

#pragma unroll
        for (int i = 0; i < 4; ++i) {
            float mx = fmaxf(fmaxf(s[i][0], s[i][1]), fmaxf(s[i][2], s[i][3]));
#pragma unroll
            for (int off = 1; off < 16; off <<= 1)
                mx = fmaxf(mx, __shfl_xor_sync(0xffffffffu, mx, off));
            float mn = fmaxf(mrow[i], mx);
            float corr = __expf(mrow[i] - mn);
            mrow[i] = mn;
            float rs = 0.f;
#pragma unroll
            for (int j = 0; j < 4; ++j) {
                float p = __expf(s[i][j] - mn);
                s[i][j] = p;
                rs += p;
            }
#pragma unroll
            for (int off = 1; off < 16; off <<= 1)
                rs += __shfl_xor_sync(0xffffffffu, rs, off);
            lrow[i] = lrow[i] * corr + rs;
#pragma unroll
            for (int d = 0; d < 8; ++d) o[i][d] *= corr;
            *(float4*)&Ps[(4 * ty + i) * QS_PAD + 4 * tx] =
                make_float4(s[i][0], s[i][1], s[i][2], s[i][3]);
        }
        __syncthreads();

        for (int kp = 0; kp < FBN; ++kp) {
            float4 v0 = *(const float4*)&Vs[kp * DH + tx * 8];
            float4 v1 = *(const float4*)&Vs[kp * DH + tx * 8 + 4];
#pragma unroll
            for (int i = 0; i < 4; ++i) {
                float p = Ps[(4 * ty + i) * QS_PAD + kp];
                o[i][0] += p * v0.x;
                o[i][1] += p * v0.y;
                o[i][2] += p * v0.z;
                o[i][3] += p * v0.w;
                o[i][4] += p * v1.x;
                o[i][5] += p * v1.y;
                o[i][6] += p * v1.z;
                o[i][7] += p * v1.w;
            }
        }
    }

#pragma unroll
    for (int i = 0; i < 4; ++i) {
        float inv = 1.f / lrow[i];
        int row = qt * FBM + 4 * ty + i;
        float* op = attn + (size_t)row * D_MODEL + h * DH + tx * 8;
        float4 r0 = make_float4(o[i][0] * inv, o[i][1] * inv, o[i][2] * inv, o[i][3] * inv);
        float4 r1 = make_float4(o[i][4] * inv, o[i][5] * inv, o[i][6] * inv, o[i][7] * inv);
        *(float4*)(op) = r0;
        *(float4*)(op + 4) = r1;
    }
}

// ---------------------------------------------------------------------------
extern "C" void kernel_launch(void* const* d_in, const int* in_sizes, int n_in,
                              void* d_out, int out_size)
{
    const int* positions   = (const int*)d_in[0];
    const float* hidden    = (const float*)d_in[1];
    const float* Wqkv      = (const float*)d_in[2];
    const float* bqkv      = (const float*)d_in[3];
    const float* Wo        = (const float*)d_in[4];
    float* out = (float*)d_out;

    float *qkv, *attn;
    __nv_bfloat16 *wqh, *wql, *woh, *wol, *hh, *hl, *ath, *atl;
    cudaGetSymbolAddress((void**)&qkv, g_qkv);
    cudaGetSymbolAddress((void**)&attn, g_attn);
    cudaGetSymbolAddress((void**)&wqh, g_WqkvT_h);
    cudaGetSymbolAddress((void**)&wql, g_WqkvT_l);
    cudaGetSymbolAddress((void**)&woh, g_WoT_h);
    cudaGetSymbolAddress((void**)&wol, g_WoT_l);
    cudaGetSymbolAddress((void**)&hh, g_hid_h);
    cudaGetSymbolAddress((void**)&hl, g_hid_l);
    cudaGetSymbolAddress((void**)&ath, g_att_h);
    cudaGetSymbolAddress((void**)&atl, g_att_l);

    cudaFuncSetAttribute(flash_kernel,
                         cudaFuncAttributeMaxDynamicSharedMemorySize, FLASH_SMEM_BYTES);
    cudaFuncSetAttribute(bf3_gemm_kernel,
                         cudaFuncAttributeMaxDynamicSharedMemorySize, GEMM_SMEM_BYTES);

    // 0) splits: activations plain; weights transposed to [N][K]
    splitb_kernel<<<(unsigned)(HID_ELEMS / 4 + 255) / 256, 256>>>(hidden, hh, hl, HID_ELEMS / 4);
    tsplitb_kernel<<<dim3(QKV_N / 32, D_MODEL / 32), dim3(32, 8)>>>(Wqkv, wqh, wql, D_MODEL, QKV_N);
    tsplitb_kernel<<<dim3(D_MODEL / 32, D_MODEL / 32), dim3(32, 8)>>>(Wo, woh, wol, D_MODEL, D_MODEL);

    // 1) QKV = hidden @ W_qkv + b   (3xBF16 tensor cores)
    bf3_gemm_kernel<<<dim3(QKV_N / 128, T_SEQ / 128), 256, GEMM_SMEM_BYTES>>>(
        hh, hl, wqh, wql, bqkv, qkv, T_SEQ, QKV_N, D_MODEL);

    // 2) RoPE
    rope_kernel<<<(T_SEQ * 32 * 64) / 256, 256>>>(positions, qkv);

    // 3) Flash attention
    flash_kernel<<<dim3(T_SEQ / FBM, HQ), 256, FLASH_SMEM_BYTES>>>(qkv, attn);

    // 4) split attn, then out = attn @ W_o   (3xBF16 tensor cores)
    splitb_kernel<<<(unsigned)(HID_ELEMS / 4 + 255) / 256, 256>>>(attn, ath, atl, HID_ELEMS / 4);
    bf3_gemm_kernel<<<dim3(D_MODEL / 128, T_SEQ / 128), 256, GEMM_SMEM_BYTES>>>(
        ath, atl, woh, wol, nullptr, out, T_SEQ, D_MODEL, D_MODEL);
}